// round 1
// baseline (speedup 1.0000x reference)
#include <cuda_runtime.h>
#include <cuda_bf16.h>
#include <cstdint>

// ---------------------------------------------------------------------------
// MoESystem: gate (mean-pool MLP + softmax) -> route rows to one of two
// experts -> expert MLP [1536 -> 1024 -> 2].
//
// Pipeline per launch:
//   1. init_kernel        : zero counters
//   2. prep_w_kernel      : round expert W1 weights to tf32 into scratch
//   3. gate_permute_kernel: gate per row, write dec/prob to d_out, copy row
//                           (tf32-rounded) into partitioned scratch
//                           (normal rows from 0 up, abnormal from B down)
//   4. gemm_kernel        : tf32 mma.sync GEMM [B x 1536] @ [1536 x 1024],
//                           fused bias+relu+layer2 epilogue -> per-Ntile
//                           partial y into g_ypart
//   5. finalize_kernel    : sum 8 partials + b2, scatter to original rows
// ---------------------------------------------------------------------------

#define T_DIM 48
#define D_DIM 32
#define TD 1536
#define H_DIM 1024
#define GH 128
#define MAXB 16384
#define W1SZ (TD * H_DIM)

#define BM 128
#define BN 128
#define BK 32
#define LDA 36   // 128x36 floats, (r*36+qc) % 32 distinct across lanes
#define LDB 136  // 32x136 floats, (k*136+n) % 32 distinct across lanes
#define ASZ (BM * LDA)
#define BSZ (BK * LDB)
#define SMEM_BYTES ((2 * ASZ + 2 * BSZ) * 4)

// Scratch (device globals: allocation-free)
__device__ float g_xp[(size_t)MAXB * TD];       // permuted, tf32-rounded x
__device__ float g_w1t[2 * W1SZ];               // tf32-rounded W1 (normal, abnormal)
__device__ float g_ypart[8 * MAXB * 2];         // per-Ntile layer-2 partials
__device__ int   g_src[MAXB];                   // permuted pos -> original row
__device__ int   g_cnt[2];                      // [0]=normal count, [1]=abnormal count

__device__ __forceinline__ float rtf32(float f) {
    unsigned u;
    asm("cvt.rna.tf32.f32 %0, %1;" : "=r"(u) : "f"(f));
    return __uint_as_float(u);
}

__device__ __forceinline__ void cpa16(float* s, const float* g) {
    unsigned sa = (unsigned)__cvta_generic_to_shared(s);
    asm volatile("cp.async.cg.shared.global [%0], [%1], 16;" :: "r"(sa), "l"(g));
}

__device__ __forceinline__ void mma_tf32(float c[4], const unsigned a[4],
                                         unsigned b0, unsigned b1) {
    asm volatile(
        "mma.sync.aligned.m16n8k8.row.col.f32.tf32.tf32.f32 "
        "{%0,%1,%2,%3}, {%4,%5,%6,%7}, {%8,%9}, {%0,%1,%2,%3};"
        : "+f"(c[0]), "+f"(c[1]), "+f"(c[2]), "+f"(c[3])
        : "r"(a[0]), "r"(a[1]), "r"(a[2]), "r"(a[3]), "r"(b0), "r"(b1));
}

// ---------------------------------------------------------------------------
__global__ void init_kernel() {
    if (threadIdx.x == 0 && blockIdx.x == 0) {
        g_cnt[0] = 0;
        g_cnt[1] = 0;
    }
}

// ---------------------------------------------------------------------------
__global__ void prep_w_kernel(const float* __restrict__ nW1,
                              const float* __restrict__ aW1) {
    for (int i = blockIdx.x * blockDim.x + threadIdx.x; i < W1SZ;
         i += gridDim.x * blockDim.x) {
        g_w1t[i] = rtf32(nW1[i]);
        g_w1t[W1SZ + i] = rtf32(aW1[i]);
    }
}

// ---------------------------------------------------------------------------
// One warp per sample: gate MLP + row copy into partitioned scratch.
__global__ __launch_bounds__(256) void gate_permute_kernel(
    const float* __restrict__ x, const float* __restrict__ gW1,
    const float* __restrict__ gb1, const float* __restrict__ gW2,
    const float* __restrict__ gb2, float* __restrict__ dout, int B,
    int out_size) {
    __shared__ float sW1[D_DIM * GH];
    __shared__ float sb1[GH];
    __shared__ float sW2[GH * 2];

    for (int i = threadIdx.x; i < D_DIM * GH; i += blockDim.x) sW1[i] = gW1[i];
    for (int i = threadIdx.x; i < GH; i += blockDim.x) sb1[i] = gb1[i];
    for (int i = threadIdx.x; i < GH * 2; i += blockDim.x) sW2[i] = gW2[i];
    __syncthreads();

    int warp = threadIdx.x >> 5;
    int lane = threadIdx.x & 31;
    int b = blockIdx.x * (blockDim.x >> 5) + warp;
    if (b >= B) return;

    const float* row = x + (size_t)b * TD;

    // mean over T for d = lane
    float s = 0.f;
#pragma unroll
    for (int t = 0; t < T_DIM; t++) s += row[t * D_DIM + lane];
    float mean = s / 48.0f;

    // layer 1: each lane computes 4 hidden units
    float a0 = sb1[lane], a1 = sb1[lane + 32], a2 = sb1[lane + 64],
          a3 = sb1[lane + 96];
#pragma unroll
    for (int d = 0; d < 32; d++) {
        float md = __shfl_sync(0xffffffffu, mean, d);
        a0 += md * sW1[d * GH + lane];
        a1 += md * sW1[d * GH + lane + 32];
        a2 += md * sW1[d * GH + lane + 64];
        a3 += md * sW1[d * GH + lane + 96];
    }
    a0 = fmaxf(a0, 0.f);
    a1 = fmaxf(a1, 0.f);
    a2 = fmaxf(a2, 0.f);
    a3 = fmaxf(a3, 0.f);

    // layer 2 partials
    float z0p = a0 * sW2[lane * 2] + a1 * sW2[(lane + 32) * 2] +
                a2 * sW2[(lane + 64) * 2] + a3 * sW2[(lane + 96) * 2];
    float z1p = a0 * sW2[lane * 2 + 1] + a1 * sW2[(lane + 32) * 2 + 1] +
                a2 * sW2[(lane + 64) * 2 + 1] + a3 * sW2[(lane + 96) * 2 + 1];
#pragma unroll
    for (int off = 16; off > 0; off >>= 1) {
        z0p += __shfl_xor_sync(0xffffffffu, z0p, off);
        z1p += __shfl_xor_sync(0xffffffffu, z1p, off);
    }
    float z0 = z0p + gb2[0];
    float z1 = z1p + gb2[1];

    float prob = 1.0f / (1.0f + expf(-fabsf(z1 - z0)));
    int dec = (z1 > z0) ? 1 : 0;
    bool abn = (prob >= 0.7f) && (dec == 1);

    int p = 0;
    if (lane == 0) {
        if (abn) {
            int ia = atomicAdd(&g_cnt[1], 1);
            p = B - 1 - ia;
        } else {
            p = atomicAdd(&g_cnt[0], 1);
        }
        g_src[p] = b;
        if (2 * B + b < out_size) dout[2 * B + b] = (float)dec;
        if (3 * B + b < out_size) dout[3 * B + b] = prob;
    }
    p = __shfl_sync(0xffffffffu, p, 0);

    // copy row, rounded to tf32
    const float4* src4 = (const float4*)row;
    float4* dst4 = (float4*)(g_xp + (size_t)p * TD);
#pragma unroll 4
    for (int i = lane; i < TD / 4; i += 32) {
        float4 v = src4[i];
        v.x = rtf32(v.x);
        v.y = rtf32(v.y);
        v.z = rtf32(v.z);
        v.w = rtf32(v.w);
        dst4[i] = v;
    }
}

// ---------------------------------------------------------------------------
// grid (8 Ntiles, B/128 Mtiles), 256 threads (8 warps, 4x2), warp tile 32x64.
__global__ __launch_bounds__(256, 2) void gemm_kernel(
    const float* __restrict__ nb1, const float* __restrict__ ab1,
    const float* __restrict__ nW2, const float* __restrict__ aW2, int B) {
    extern __shared__ float smem[];
    float* As = smem;
    float* Bs = smem + 2 * ASZ;

    const int nt = blockIdx.x;
    const int m0 = blockIdx.y * BM;
    const int n0 = nt * BN;
    const int split = g_cnt[0];

    const int warp = threadIdx.x >> 5;
    const int lane = threadIdx.x & 31;
    const int wm = warp >> 1;  // 0..3
    const int wn = warp & 1;   // 0..1
    const int qr = lane >> 2;  // 0..7
    const int qc = lane & 3;   // 0..3

    const int e_lo = (m0 < split) ? 0 : 1;
    const int e_hi = (m0 + BM - 1 < split) ? 0 : 1;

    for (int e = e_lo; e <= e_hi; e++) {
        const float* W1 = g_w1t + (size_t)e * W1SZ;
        const float* bias1 = e ? ab1 : nb1;
        const float* w2 = e ? aW2 : nW2;

        float c[2][8][4];
#pragma unroll
        for (int mi = 0; mi < 2; mi++)
#pragma unroll
            for (int ni = 0; ni < 8; ni++)
#pragma unroll
                for (int k = 0; k < 4; k++) c[mi][ni][k] = 0.f;

        // ---- tile loader ----
        auto load_tile = [&](int kb, int buf) {
            const int k0 = kb * BK;
            float* As_ = As + buf * ASZ;
            float* Bs_ = Bs + buf * BSZ;
#pragma unroll
            for (int i = 0; i < 4; i++) {
                int f = threadIdx.x + 256 * i;
                int r = f >> 3, c4 = f & 7;
                cpa16(As_ + r * LDA + c4 * 4,
                      g_xp + (size_t)(m0 + r) * TD + k0 + c4 * 4);
            }
#pragma unroll
            for (int i = 0; i < 4; i++) {
                int f = threadIdx.x + 256 * i;
                int kr = f >> 5, c4 = f & 31;
                cpa16(Bs_ + kr * LDB + c4 * 4,
                      W1 + (size_t)(k0 + kr) * H_DIM + n0 + c4 * 4);
            }
        };

        load_tile(0, 0);
        asm volatile("cp.async.commit_group;");

        const int KB = TD / BK;  // 48
        for (int kb = 0; kb < KB; kb++) {
            int buf = kb & 1;
            if (kb + 1 < KB) {
                load_tile(kb + 1, (kb + 1) & 1);
                asm volatile("cp.async.commit_group;");
                asm volatile("cp.async.wait_group 1;");
            } else {
                asm volatile("cp.async.wait_group 0;");
            }
            __syncthreads();

            const float* As_ = As + buf * ASZ;
            const float* Bs_ = Bs + buf * BSZ;
#pragma unroll
            for (int ks = 0; ks < 4; ks++) {
                unsigned a[2][4];
#pragma unroll
                for (int mi = 0; mi < 2; mi++) {
                    int r0 = wm * 32 + mi * 16 + qr;
                    a[mi][0] = __float_as_uint(As_[r0 * LDA + ks * 8 + qc]);
                    a[mi][1] =
                        __float_as_uint(As_[(r0 + 8) * LDA + ks * 8 + qc]);
                    a[mi][2] =
                        __float_as_uint(As_[r0 * LDA + ks * 8 + qc + 4]);
                    a[mi][3] =
                        __float_as_uint(As_[(r0 + 8) * LDA + ks * 8 + qc + 4]);
                }
#pragma unroll
                for (int ni = 0; ni < 8; ni++) {
                    int col = wn * 64 + ni * 8 + qr;
                    unsigned b0 =
                        __float_as_uint(Bs_[(ks * 8 + qc) * LDB + col]);
                    unsigned b1 =
                        __float_as_uint(Bs_[(ks * 8 + qc + 4) * LDB + col]);
                    mma_tf32(c[0][ni], a[0], b0, b1);
                    mma_tf32(c[1][ni], a[1], b0, b1);
                }
            }
            __syncthreads();
        }

        // ---- epilogue: bias + relu + layer2, reduce to y[row][2] ----
        float* ysum = smem;  // reuse (256 floats)
        if (threadIdx.x < 256) ysum[threadIdx.x] = 0.f;
        __syncthreads();

#pragma unroll
        for (int mi = 0; mi < 2; mi++) {
            int rloc = wm * 32 + mi * 16 + qr;
            float ylo0 = 0.f, ylo1 = 0.f, yhi0 = 0.f, yhi1 = 0.f;
#pragma unroll
            for (int ni = 0; ni < 8; ni++) {
                int colg = n0 + wn * 64 + ni * 8 + 2 * qc;
                float h0 = fmaxf(c[mi][ni][0] + bias1[colg], 0.f);
                float h1 = fmaxf(c[mi][ni][1] + bias1[colg + 1], 0.f);
                float h2 = fmaxf(c[mi][ni][2] + bias1[colg], 0.f);
                float h3 = fmaxf(c[mi][ni][3] + bias1[colg + 1], 0.f);
                float w00 = w2[colg * 2], w01 = w2[colg * 2 + 1];
                float w10 = w2[(colg + 1) * 2], w11 = w2[(colg + 1) * 2 + 1];
                ylo0 += h0 * w00 + h1 * w10;
                ylo1 += h0 * w01 + h1 * w11;
                yhi0 += h2 * w00 + h3 * w10;
                yhi1 += h2 * w01 + h3 * w11;
            }
#pragma unroll
            for (int off = 1; off < 4; off <<= 1) {
                ylo0 += __shfl_xor_sync(0xffffffffu, ylo0, off);
                ylo1 += __shfl_xor_sync(0xffffffffu, ylo1, off);
                yhi0 += __shfl_xor_sync(0xffffffffu, yhi0, off);
                yhi1 += __shfl_xor_sync(0xffffffffu, yhi1, off);
            }
            if (qc == 0) {
                atomicAdd(&ysum[rloc * 2 + 0], ylo0);
                atomicAdd(&ysum[rloc * 2 + 1], ylo1);
                atomicAdd(&ysum[(rloc + 8) * 2 + 0], yhi0);
                atomicAdd(&ysum[(rloc + 8) * 2 + 1], yhi1);
            }
        }
        __syncthreads();

        // store rows belonging to this expert's region
        {
            int row = threadIdx.x >> 1;
            int j = threadIdx.x & 1;
            int p = m0 + row;
            int rowExp = (p >= split) ? 1 : 0;
            if (rowExp == e)
                g_ypart[((size_t)nt * B + p) * 2 + j] = ysum[threadIdx.x];
        }
        __syncthreads();
    }
}

// ---------------------------------------------------------------------------
__global__ void finalize_kernel(const float* __restrict__ nb2,
                                const float* __restrict__ ab2,
                                float* __restrict__ dout, int B,
                                int out_size) {
    int p = blockIdx.x * blockDim.x + threadIdx.x;
    if (p >= B) return;
    int split = g_cnt[0];
    int b = g_src[p];
    const float* b2 = (p < split) ? nb2 : ab2;
    float y0 = 0.f, y1 = 0.f;
#pragma unroll
    for (int nt = 0; nt < 8; nt++) {
        y0 += g_ypart[((size_t)nt * B + p) * 2 + 0];
        y1 += g_ypart[((size_t)nt * B + p) * 2 + 1];
    }
    if (b * 2 + 1 < out_size) {
        dout[b * 2 + 0] = y0 + b2[0];
        dout[b * 2 + 1] = y1 + b2[1];
    }
}

// ---------------------------------------------------------------------------
extern "C" void kernel_launch(void* const* d_in, const int* in_sizes, int n_in,
                              void* d_out, int out_size) {
    const float* x = (const float*)d_in[0];
    const float* gW1 = (const float*)d_in[1];
    const float* gb1 = (const float*)d_in[2];
    const float* gW2 = (const float*)d_in[3];
    const float* gb2 = (const float*)d_in[4];
    const float* nW1 = (const float*)d_in[5];
    const float* nb1 = (const float*)d_in[6];
    const float* nW2 = (const float*)d_in[7];
    const float* nb2 = (const float*)d_in[8];
    const float* aW1 = (const float*)d_in[9];
    const float* ab1 = (const float*)d_in[10];
    const float* aW2 = (const float*)d_in[11];
    const float* ab2 = (const float*)d_in[12];

    int B = in_sizes[0] / TD;
    float* out = (float*)d_out;

    cudaFuncSetAttribute(gemm_kernel,
                         cudaFuncAttributeMaxDynamicSharedMemorySize,
                         SMEM_BYTES);

    init_kernel<<<1, 32>>>();
    prep_w_kernel<<<1536, 256>>>(nW1, aW1);
    gate_permute_kernel<<<(B + 7) / 8, 256>>>(x, gW1, gb1, gW2, gb2, out, B,
                                              out_size);
    dim3 grid(H_DIM / BN, B / BM);
    gemm_kernel<<<grid, 256, SMEM_BYTES>>>(nb1, ab1, nW2, aW2, B);
    finalize_kernel<<<(B + 255) / 256, 256>>>(nb2, ab2, out, B, out_size);
}